// round 14
// baseline (speedup 1.0000x reference)
#include <cuda_runtime.h>
#include <math.h>

typedef unsigned long long ull;

#define NDIM 512
#define DDIM 784
#define CDIM 10
#define ITERS 40
#define QMAX 127.0f

#define MT 8          // row tiles (64 rows each)
#define NT 16         // column groups (8 cols each)
#define GRID (MT*NT)  // 128 CTAs
#define TPB 512
#define ZSTR 12       // padded z row stride (8 used + 4 pad)

// shared layout (float offsets)
#define S_Z    0          // 512*12 = 6144 (single buffer, per-warp row ownership)
#define S_RED  6144       // DOUBLE buffered: 2 x (16 warps * 640) = 20480
#define S_UX   26624      // 512
#define SMEM_FLOATS 27200
#define SMEM_BYTES (SMEM_FLOATS*4)
// Phase B scratch overlaps S_Z/S_RED: xs @0 (6272), uq @6272 (7424, ends 13696)

// ---- device globals (scratch) ----
__device__ float g_zA[NDIM*128];                 // z_j, j odd
__device__ float g_zB[NDIM*128];                 // z_j, j even
__device__ unsigned g_rgen[2][NT*NDIM];          // per-row generation words
__device__ unsigned g_maxW, g_maxU, g_maxB;      // idempotent atomicMax
__device__ unsigned g_gcnt, g_ggen;              // grid barrier (used once)

// -------- grid barrier (prologue only) --------
__device__ __forceinline__ void gbar(unsigned* cnt, unsigned* gen, unsigned expected) {
    __syncthreads();
    if (threadIdx.x == 0) {
        unsigned snap, t;
        asm volatile("ld.acquire.gpu.global.u32 %0, [%1];" : "=r"(snap) : "l"(gen) : "memory");
        asm volatile("atom.acq_rel.gpu.global.add.u32 %0, [%1], %2;"
                     : "=r"(t) : "l"(cnt), "r"(1u) : "memory");
        if (t == expected - 1u) {
            asm volatile("st.relaxed.gpu.global.u32 [%0], %1;" :: "l"(cnt), "r"(0u) : "memory");
            asm volatile("red.release.gpu.global.add.u32 [%0], %1;" :: "l"(gen), "r"(1u) : "memory");
        } else {
            unsigned g;
            do {
                asm volatile("ld.acquire.gpu.global.u32 %0, [%1];" : "=r"(g) : "l"(gen) : "memory");
            } while (g == snap);
        }
    }
    __syncthreads();
}

// -------- gen-word primitives --------
__device__ __forceinline__ void gen_store(unsigned* f, unsigned v) {
    asm volatile("st.release.gpu.global.u32 [%0], %1;" :: "l"(f), "r"(v) : "memory");
}
__device__ __forceinline__ unsigned gen_acq(const unsigned* f) {
    unsigned v;
    asm volatile("ld.acquire.gpu.global.u32 %0, [%1];" : "=r"(v) : "l"(f) : "memory");
    return v;
}

// -------- f32x2 helpers --------
__device__ __forceinline__ ull pk2(float x){
    ull d; asm("mov.b64 %0, {%1,%1};" : "=l"(d) : "r"(__float_as_uint(x))); return d;
}
__device__ __forceinline__ void fma2(ull& d, ull a, ull b){
    asm("fma.rn.f32x2 %0, %1, %2, %3;" : "=l"(d) : "l"(a), "l"(b), "l"(d));
}
__device__ __forceinline__ float warpmax(float v){
    #pragma unroll
    for (int o = 16; o; o >>= 1) v = fmaxf(v, __shfl_xor_sync(0xffffffffu, v, o));
    return v;
}

extern "C" __global__ void __launch_bounds__(TPB, 1)
mondeq_kernel(const float* __restrict__ W, const float* __restrict__ U,
              const float* __restrict__ bvec, const float* __restrict__ x,
              const float* __restrict__ Wc, const float* __restrict__ bcv,
              float* __restrict__ out)
{
    extern __shared__ float sm[];
    float* sZ   = sm + S_Z;
    float* sRed = sm + S_RED;
    float* sUx  = sm + S_UX;

    const int tid  = threadIdx.x;
    const int cta  = blockIdx.x;
    const int mi   = cta & (MT - 1);   // row tile 0..7
    const int nj   = cta >> 3;         // column group 0..15
    const int wid  = tid >> 5;         // warp: k within tile = wid*4 + j2
    const int lane = tid & 31;         // rows 2*lane, 2*lane+1 of own tile

    // ================= Phase A: per-tensor max|.| (idempotent atomicMax) ==========
    {
        float lw = 0.f, lu = 0.f, lb = 0.f;
        const int gid = cta * TPB + tid;
        for (int i = gid; i < NDIM*NDIM; i += GRID*TPB) lw = fmaxf(lw, fabsf(W[i]));
        for (int i = gid; i < NDIM*DDIM; i += GRID*TPB) lu = fmaxf(lu, fabsf(U[i]));
        if (gid < NDIM) lb = fabsf(bvec[gid]);
        lw = warpmax(lw); lu = warpmax(lu); lb = warpmax(lb);
        if (lane == 0) { sm[wid] = lw; sm[16 + wid] = lu; sm[32 + wid] = lb; }
        __syncthreads();
        if (tid == 0) {
            float mw = 0.f, mu = 0.f, mb = 0.f;
            #pragma unroll
            for (int i = 0; i < 16; ++i) {
                mw = fmaxf(mw, sm[i]); mu = fmaxf(mu, sm[16+i]); mb = fmaxf(mb, sm[32+i]);
            }
            atomicMax(&g_maxW, __float_as_uint(mw));
            atomicMax(&g_maxU, __float_as_uint(mu));
            atomicMax(&g_maxB, __float_as_uint(mb));
        }
    }
    gbar(&g_gcnt, &g_ggen, GRID);   // the ONLY grid barrier

    const float scW = __uint_as_float(__ldcg(&g_maxW)) / QMAX;
    const float scU = __uint_as_float(__ldcg(&g_maxU)) / QMAX;
    const float scB = __uint_as_float(__ldcg(&g_maxB)) / QMAX;

    // ================= Phase B (group-local): Ux = Uq @ x^T + bq ===================
    {
        float* xs = sm;            // [784][8] transposed x cols (6272)
        float* uq = sm + 6272;     // [64][116] quantized U chunk (7424)
        const int r = tid >> 3;
        const int c = tid & 7;
        for (int i = tid; i < DDIM*8; i += TPB) {
            const int k = i >> 3, cc = i & 7;
            xs[i] = x[(size_t)(nj*8 + cc)*DDIM + k];
        }
        float acc = 0.f;
        for (int ch = 0; ch < 7; ++ch) {
            __syncthreads();
            for (int i = tid; i < 64*112; i += TPB) {
                const int rr = i / 112, kk = i - rr*112;
                uq[rr*116 + kk] = rintf(U[(size_t)(mi*64 + rr)*DDIM + ch*112 + kk] / scU) * scU;
            }
            __syncthreads();
            const float* up = uq + r*116;
            const float* xp = xs + ch*112*8 + c;
            #pragma unroll 4
            for (int kk = 0; kk < 112; ++kk)
                acc = fmaf(up[kk], xp[kk*8], acc);
        }
        const float bq = rintf(bvec[mi*64 + r] / scB) * scB;
        __syncthreads();                 // uq/xs reads done before sZ/sRed reuse
        sUx[tid] = acc + bq;
    }

    // ================= Phase C: quantized W -> per-thread scalar registers =========
    float w0[32], w1[32];
    {
        const float* Wr0 = W + (size_t)(mi*64 + 2*lane)*NDIM;
        const float* Wr1 = Wr0 + NDIM;
        #pragma unroll
        for (int t = 0; t < 8; ++t) {
            const int k0 = t*64 + wid*4;
            const float4 a = *(const float4*)(Wr0 + k0);
            const float4 b = *(const float4*)(Wr1 + k0);
            w0[t*4+0] = rintf(a.x/scW)*scW; w0[t*4+1] = rintf(a.y/scW)*scW;
            w0[t*4+2] = rintf(a.z/scW)*scW; w0[t*4+3] = rintf(a.w/scW)*scW;
            w1[t*4+0] = rintf(b.x/scW)*scW; w1[t*4+1] = rintf(b.y/scW)*scW;
            w1[t*4+2] = rintf(b.z/scW)*scW; w1[t*4+3] = rintf(b.w/scW)*scW;
        }
    }

    // per-thread z output coordinates (combine mapping)
    const int orow = tid >> 3;           // own-tile row 0..63
    const int ocol = tid & 7;
    const int growN = mi*64 + orow;      // global row within group
    unsigned* rg0 = &g_rgen[0][nj*NDIM]; // gen words, buffer A (odd j)
    unsigned* rg1 = &g_rgen[1][nj*NDIM]; // gen words, buffer B (even j)

    // ================= z1 = relu(0.5*Ux): local + publish (data + gen) =============
    float z_prev;
    {
        const float z1 = fmaxf(0.5f * sUx[tid], 0.f);
        z_prev = z1;
        sZ[growN*ZSTR + ocol] = z1;
        __stcg(&g_zA[nj*4096 + mi*512 + tid], z1);
        __syncwarp();
        if (ocol == 0) gen_store(&rg0[growN], 1u);
    }
    float* gz_cur = g_zA;
    float* gz_nxt = g_zB;
    unsigned* rg_cur = rg0;
    unsigned* rg_nxt = rg1;

    // per-warp staging assignment: lane < 28 stages one remote row it will consume
    int st_row = -1;
    if (lane < 28) {
        int t = lane >> 2; t += (t >= mi);
        st_row = t*64 + wid*4 + (lane & 3);
    }

    // ================= Main loop: 39 iterations (z2..z40) ==========================
    for (int it = 2; it <= ITERS; ++it) {
        const int rb = it & 1;                 // sRed buffer for this iteration
        float* sRb = sRed + rb*10240;
        ull a00=0,a01=0,a02=0,a03=0, a10=0,a11=0,a12=0,a13=0;

        // ---- own-tile GEMM first (rows wid*4..+3 written by THIS warp's combine) --
        {
            const float* zt = sZ + (mi*64 + wid*4)*ZSTR;
            #pragma unroll
            for (int j2 = 0; j2 < 4; ++j2) {
                const float* q = zt + j2*ZSTR;
                const ulonglong2 zA = *(const ulonglong2*)(q);
                const ulonglong2 zB = *(const ulonglong2*)(q + 4);
                const ull wd0 = pk2(w0[mi*4+j2]);
                const ull wd1 = pk2(w1[mi*4+j2]);
                fma2(a00, wd0, zA.x); fma2(a01, wd0, zA.y);
                fma2(a02, wd0, zB.x); fma2(a03, wd0, zB.y);
                fma2(a10, wd1, zA.x); fma2(a11, wd1, zA.y);
                fma2(a12, wd1, zB.x); fma2(a13, wd1, zB.y);
            }
        }

        // ---- per-lane: poll row gen (data self-announces), then stage the row ----
        const unsigned tg = (unsigned)(it - 1);
        if (lane < 28) {
            const unsigned* gw = &rg_cur[st_row];
            while (gen_acq(gw) != tg) { }
            const float* src = gz_cur + nj*4096 + st_row*8;
            const float4 a = __ldcg((const float4*)src);
            const float4 b = __ldcg((const float4*)(src + 4));
            *(float4*)(sZ + st_row*ZSTR)     = a;
            *(float4*)(sZ + st_row*ZSTR + 4) = b;
        }
        __syncwarp();

        // ---- GEMM over the 7 remote tiles ----
        #pragma unroll
        for (int t = 0; t < 8; ++t) {
            if (t == mi) continue;
            const float* zt = sZ + (t*64 + wid*4)*ZSTR;
            #pragma unroll
            for (int j2 = 0; j2 < 4; ++j2) {
                const float* q = zt + j2*ZSTR;
                const ulonglong2 zA = *(const ulonglong2*)(q);
                const ulonglong2 zB = *(const ulonglong2*)(q + 4);
                const ull wd0 = pk2(w0[t*4+j2]);
                const ull wd1 = pk2(w1[t*4+j2]);
                fma2(a00, wd0, zA.x); fma2(a01, wd0, zA.y);
                fma2(a02, wd0, zB.x); fma2(a03, wd0, zB.y);
                fma2(a10, wd1, zA.x); fma2(a11, wd1, zA.y);
                fma2(a12, wd1, zB.x); fma2(a13, wd1, zB.y);
            }
        }

        // ---- partials: double-buffered sRed[rb][wid*640 + lane*20 + {0..15}] ----
        {
            float* rp = sRb + wid*640 + lane*20;
            ulonglong2 s0; s0.x = a00; s0.y = a01; *(ulonglong2*)(rp)      = s0;
            ulonglong2 s1; s1.x = a02; s1.y = a03; *(ulonglong2*)(rp + 4)  = s1;
            ulonglong2 s2; s2.x = a10; s2.y = a11; *(ulonglong2*)(rp + 8)  = s2;
            ulonglong2 s3; s3.x = a12; s3.y = a13; *(ulonglong2*)(rp + 12) = s3;
        }
        __syncthreads();   // the single per-iteration CTA join (K reduction)

        // ---- combine + relu + publish (data, then warp-fenced gen) ----
        {
            const int coff = (tid >> 4)*20 + ((tid >> 3) & 1)*8 + (tid & 7);
            float s = 0.f;
            const float* rq = sRb + coff;
            #pragma unroll
            for (int q = 0; q < 16; ++q) s += rq[q*640];
            const float u  = sUx[tid];
            const float v  = fmaf(0.5f, z_prev, 0.5f * (s + u));
            const float zn = fmaxf(v, 0.f);
            z_prev = zn;
            sZ[growN*ZSTR + ocol] = zn;
            __stcg(&gz_nxt[nj*4096 + mi*512 + tid], zn);
            __syncwarp();          // warp's 4 rows fully stored (smem + global)
            if (ocol == 0) gen_store(&rg_nxt[growN], (unsigned)it);
        }

        { float* t = gz_cur; gz_cur = gz_nxt; gz_nxt = t; }
        { unsigned* t = rg_cur; rg_cur = rg_nxt; rg_nxt = t; }
    }

    // ================= Classifier (row-tile 0 CTA of each group) ====================
    if (mi == 0) {
        // stage z40 (buffer B, gen 40): one thread per global row
        {
            const unsigned* gw = &rg1[tid];
            while (gen_acq(gw) != (unsigned)ITERS) { }
            const float* src = g_zB + nj*4096 + tid*8;
            const float4 a = __ldcg((const float4*)src);
            const float4 b = __ldcg((const float4*)(src + 4));
            *(float4*)(sZ + tid*ZSTR)     = a;
            *(float4*)(sZ + tid*ZSTR + 4) = b;
        }
        __syncthreads();
        if (tid < 8*CDIM) {
            const int bl = tid / CDIM, cc = tid - bl*CDIM;
            const float* wc = Wc + cc*NDIM;
            float acc = bcv[cc];
            #pragma unroll 8
            for (int n = 0; n < NDIM; ++n)
                acc = fmaf(sZ[n*ZSTR + bl], wc[n], acc);
            out[(nj*8 + bl)*CDIM + cc] = acc;
        }
    }
}

extern "C" void kernel_launch(void* const* d_in, const int* in_sizes, int n_in,
                              void* d_out, int out_size) {
    (void)in_sizes; (void)n_in; (void)out_size;
    cudaFuncSetAttribute(mondeq_kernel, cudaFuncAttributeMaxDynamicSharedMemorySize, SMEM_BYTES);
    mondeq_kernel<<<GRID, TPB, SMEM_BYTES>>>(
        (const float*)d_in[0],   // W  (512,512)
        (const float*)d_in[1],   // U  (512,784)
        (const float*)d_in[2],   // b  (512)
        (const float*)d_in[3],   // x  (128,784)
        (const float*)d_in[4],   // Wc (10,512)
        (const float*)d_in[5],   // bc (10)
        (float*)d_out);          // logits (128,10)
}